// round 7
// baseline (speedup 1.0000x reference)
#include <cuda_runtime.h>
#include <cstdint>

// Gate_60421599920823 : MoE sigmoid gating (fp32 FFMA2 path; tcgen05 unavailable:
// harness ptxas targets sm_103 without the 'a' feature suffix).
//   logits = x[8192,4096] @ W^T[4096,64] (fp32)
//   scores = sigmoid(logits); top-2 on (scores + bias); weights normalized.
// Output: [weights N*2 | indices-as-float N*2 | scores N*64] (validated round 3)

#define D_DIM    4096
#define NEXP     64
#define TILE_M   64
#define KC       64
#define NC       (D_DIM / KC)      // 64
#define THREADS  256
#define NBUF     3
#define XPITCH   68                // floats per X row (272B: 16B aligned, bank-rotating)

// dynamic smem layout (bytes)
#define X_STAGE_BYTES  (TILE_M * XPITCH * 4)        // 17408
#define W_STAGE_BYTES  (NEXP * KC * 4)              // 16384
#define X_OFF(b)       ((b) * X_STAGE_BYTES)
#define W_OFF(b)       (NBUF * X_STAGE_BYTES + (b) * W_STAGE_BYTES)
#define SMEM_TOTAL     (NBUF * (X_STAGE_BYTES + W_STAGE_BYTES))   // 101376
#define C_STRIDE       68

typedef unsigned long long ull;

__device__ __forceinline__ void ffma2(ull& d, ull a, ull b) {
    asm("fma.rn.f32x2 %0, %1, %2, %3;" : "=l"(d) : "l"(a), "l"(b), "l"(d));
}

__global__ __launch_bounds__(THREADS, 1)
void gate_kernel(const float* __restrict__ x,
                 const float* __restrict__ w,
                 const float* __restrict__ bias,
                 float* __restrict__ out_w,
                 float* __restrict__ out_i,
                 float* __restrict__ out_s)
{
    extern __shared__ char smem[];
    float* Xs = (float*)smem;                         // [NBUF][TILE_M][XPITCH]
    float* Ws = (float*)(smem + W_OFF(0));            // [NBUF][NEXP][KC] swizzled

    const int tid = threadIdx.x;
    const int tx  = tid & 15;      // expert group: e = tx + 16j, j=0..3
    const int ty  = tid >> 4;      // row group: rows ty*4 .. ty*4+3
    const int row_base = blockIdx.x * TILE_M;

    // ---- async chunk loader (4 X-float4 + 4 W-float4 per thread) ----------
    auto load_chunk = [&](int c, int buf) {
        const int k0 = c * KC;
        const float* Xb = (const float*)(smem + X_OFF(buf));
        const float* Wb = (const float*)(smem + W_OFF(buf));
        #pragma unroll
        for (int i = 0; i < 4; ++i) {                 // X: 64 rows x 16 float4
            int lin = tid + i * THREADS;              // 0..1023
            int r   = lin >> 4;
            int c4  = lin & 15;
            const float* src = x + (size_t)(row_base + r) * D_DIM + k0 + c4 * 4;
            uint32_t dst = (uint32_t)__cvta_generic_to_shared(&Xb[r * XPITCH + c4 * 4]);
            asm volatile("cp.async.cg.shared.global [%0], [%1], 16;\n" :: "r"(dst), "l"(src));
        }
        #pragma unroll
        for (int i = 0; i < 4; ++i) {                 // W: 64 rows x 16 float4, XOR-16 swizzle
            int lin = tid + i * THREADS;
            int r   = lin >> 4;
            int c4  = lin & 15;
            const float* src = w + (size_t)r * D_DIM + k0 + c4 * 4;
            int sw = c4 ^ (r & 15);
            uint32_t dst = (uint32_t)__cvta_generic_to_shared(&Wb[r * KC + sw * 4]);
            asm volatile("cp.async.cg.shared.global [%0], [%1], 16;\n" :: "r"(dst), "l"(src));
        }
        asm volatile("cp.async.commit_group;\n");
    };

    // ---- mainloop ----------------------------------------------------------
    ull acc[4][4];
    #pragma unroll
    for (int r = 0; r < 4; ++r)
        #pragma unroll
        for (int j = 0; j < 4; ++j) acc[r][j] = 0ULL;

    load_chunk(0, 0);
    load_chunk(1, 1);

    for (int c = 0; c < NC; ++c) {
        const int buf = c % NBUF;
        if (c == NC - 1) { asm volatile("cp.async.wait_group 0;\n"); }
        else             { asm volatile("cp.async.wait_group 1;\n"); }
        __syncthreads();                              // single barrier per chunk
        if (c + 2 < NC) load_chunk(c + 2, (c + 2) % NBUF);

        const float* Xb = (const float*)(smem + X_OFF(buf));
        const float* Wb = (const float*)(smem + W_OFF(buf));

        #pragma unroll
        for (int kq = 0; kq < KC; kq += 4) {
            const int q = kq >> 2;
            float4 xv[4];
            #pragma unroll
            for (int r = 0; r < 4; ++r)
                xv[r] = *reinterpret_cast<const float4*>(&Xb[(ty * 4 + r) * XPITCH + kq]);
            float4 wv[4];
            #pragma unroll
            for (int j = 0; j < 4; ++j) {
                const int e  = tx + 16 * j;
                const int sw = q ^ tx;                // (e & 15) == tx
                wv[j] = *reinterpret_cast<const float4*>(&Wb[e * KC + sw * 4]);
            }
            #pragma unroll
            for (int r = 0; r < 4; ++r) {
                const ull* px = reinterpret_cast<const ull*>(&xv[r]);
                #pragma unroll
                for (int j = 0; j < 4; ++j) {
                    const ull* pw = reinterpret_cast<const ull*>(&wv[j]);
                    ffma2(acc[r][j], px[0], pw[0]);
                    ffma2(acc[r][j], px[1], pw[1]);
                }
            }
        }
    }
    __syncthreads();   // tiles dead; reuse smem for epilogue

    // ---- epilogue ----------------------------------------------------------
    float* C = (float*)smem;                          // [TILE_M][C_STRIDE]
    #pragma unroll
    for (int r = 0; r < 4; ++r)
        #pragma unroll
        for (int j = 0; j < 4; ++j) {
            float2 f = *reinterpret_cast<float2*>(&acc[r][j]);
            C[(ty * 4 + r) * C_STRIDE + (tx + 16 * j)] = f.x + f.y;
        }
    __syncthreads();

    // sigmoid + coalesced scores store
    for (int idx = tid; idx < TILE_M * NEXP; idx += THREADS) {
        const int r = idx >> 6, e = idx & 63;
        const float v = 1.0f / (1.0f + __expf(-C[r * C_STRIDE + e]));
        C[r * C_STRIDE + e] = v;
        if (out_s) out_s[(size_t)row_base * NEXP + idx] = v;
    }
    __syncthreads();

    // per-row top-2 (strict > keeps lowest index on ties, like lax.top_k)
    if (tid < TILE_M) {
        const int r = tid;
        float b0 = -1e30f, b1 = -1e30f;
        int   i0 = 0,      i1 = 0;
        #pragma unroll
        for (int e = 0; e < NEXP; ++e) {
            const float v = C[r * C_STRIDE + e] + bias[e];
            if (v > b0)      { b1 = b0; i1 = i0; b0 = v; i0 = e; }
            else if (v > b1) { b1 = v;  i1 = e; }
        }
        const float w0 = C[r * C_STRIDE + i0];
        const float w1 = C[r * C_STRIDE + i1];
        const float inv = 1.0f / (w0 + w1);
        const int row = row_base + r;
        if (out_w) {
            out_w[row * 2 + 0] = w0 * inv;
            out_w[row * 2 + 1] = w1 * inv;
        }
        if (out_i) {
            out_i[row * 2 + 0] = (float)i0;
            out_i[row * 2 + 1] = (float)i1;
        }
    }
}

extern "C" void kernel_launch(void* const* d_in, const int* in_sizes, int n_in,
                              void* d_out, int out_size) {
    const float* x = (const float*)d_in[0];
    const float* w = (const float*)d_in[1];
    const float* b = (const float*)d_in[2];
    const int N = in_sizes[0] / D_DIM;         // 8192

    float* out = (float*)d_out;
    float* ow = nullptr; float* oi = nullptr; float* os = nullptr;
    if (out_size >= N * (2 * 2 + NEXP)) {      // full concat [w | i | s]
        ow = out; oi = out + (size_t)N * 2; os = out + (size_t)N * 4;
    } else if (out_size == N * NEXP) {
        os = out;
    } else if (out_size == N * 4) {
        ow = out; oi = out + (size_t)N * 2;
    } else {
        ow = out;
    }

    cudaFuncSetAttribute(gate_kernel, cudaFuncAttributeMaxDynamicSharedMemorySize, SMEM_TOTAL);
    gate_kernel<<<N / TILE_M, THREADS, SMEM_TOTAL>>>(x, w, b, ow, oi, os);
}